// round 1
// baseline (speedup 1.0000x reference)
#include <cuda_runtime.h>
#include <math.h>

#define Bsz 64
#define Tt  512
#define Dd  512
#define Hh  512
#define G4  2048   // 4*H

// ---------------- static device scratch (allocation-free rule) ----------------
__device__ float        g_Z[2][Tt][G4][Bsz];   // gate preactivations, [dir][t][g][b]  (512 MB)
__device__ float        g_Wt[2][G4][Hh];       // recurrent weights transposed: Wt[dir][g][k] = W[D+k][g]
__device__ float        g_h[2][2][Hh * Bsz];   // h double buffer, [dir][parity][n*B+b]
__device__ unsigned int g_bar[Tt];             // per-step grid barrier counters

// ---------------- init: transpose W_h, zero h / barrier ----------------
__global__ void init_kernel(const float* __restrict__ Wfw, const float* __restrict__ Wbw)
{
    int idx = blockIdx.x * blockDim.x + threadIdx.x;
    int stride = gridDim.x * blockDim.x;
    const int NWT = 2 * G4 * Hh;
    float* wt = &g_Wt[0][0][0];
    for (int i = idx; i < NWT; i += stride) {
        int dir = i / (G4 * Hh);
        int rem = i - dir * (G4 * Hh);
        int g = rem / Hh;
        int k = rem - g * Hh;
        const float* W = dir ? Wbw : Wfw;
        wt[i] = W[(size_t)(Dd + k) * G4 + g];
    }
    float* hh = &g_h[0][0][0];
    for (int i = idx; i < 2 * 2 * Hh * Bsz; i += stride) hh[i] = 0.f;
    for (int i = idx; i < Tt; i += stride) g_bar[i] = 0u;
}

// ---------------- input projection: Z[dir][t][g][b] = x[b,t,:] @ W[:D, g] + bias[g] ----------------
__global__ void __launch_bounds__(256)
proj_kernel(const float* __restrict__ x,
            const float* __restrict__ W0, const float* __restrict__ bb0,
            const float* __restrict__ W1, const float* __restrict__ bb1)
{
    const int dir = blockIdx.z;
    const float* Wp = dir ? W1 : W0;
    const float* bp = dir ? bb1 : bb0;
    const int t  = blockIdx.y;            // one block row == one timestep (64 batch rows)
    const int n0 = blockIdx.x * 64;

    __shared__ float As[16][64];
    __shared__ float Bs[16][68];
    __shared__ float Cs[64][68];

    const int tid = threadIdx.x;
    const int tx = tid & 15, ty = tid >> 4;

    // A tile loader: row = b (0..63), 4 consecutive k per thread
    const int arow = tid >> 2;
    const int akq  = (tid & 3) * 4;
    const float* xrow = x + ((size_t)arow * Tt + t) * Dd;

    // B tile loader: 16 k rows x 64 n cols, float4
    const int bkk = tid >> 4;
    const int bnq = (tid & 15) * 4;

    float acc[4][4];
#pragma unroll
    for (int i = 0; i < 4; ++i)
#pragma unroll
        for (int j = 0; j < 4; ++j) acc[i][j] = 0.f;

    for (int k0 = 0; k0 < Dd; k0 += 16) {
        float4 av = *(const float4*)(xrow + k0 + akq);
        As[akq + 0][arow] = av.x;
        As[akq + 1][arow] = av.y;
        As[akq + 2][arow] = av.z;
        As[akq + 3][arow] = av.w;
        float4 bv = *(const float4*)(Wp + (size_t)(k0 + bkk) * G4 + n0 + bnq);
        *(float4*)&Bs[bkk][bnq] = bv;
        __syncthreads();
#pragma unroll
        for (int k = 0; k < 16; ++k) {
            float4 a  = *(float4*)&As[k][ty * 4];
            float4 b4 = *(float4*)&Bs[k][tx * 4];
            acc[0][0] += a.x * b4.x; acc[0][1] += a.x * b4.y; acc[0][2] += a.x * b4.z; acc[0][3] += a.x * b4.w;
            acc[1][0] += a.y * b4.x; acc[1][1] += a.y * b4.y; acc[1][2] += a.y * b4.z; acc[1][3] += a.y * b4.w;
            acc[2][0] += a.z * b4.x; acc[2][1] += a.z * b4.y; acc[2][2] += a.z * b4.z; acc[2][3] += a.z * b4.w;
            acc[3][0] += a.w * b4.x; acc[3][1] += a.w * b4.y; acc[3][2] += a.w * b4.z; acc[3][3] += a.w * b4.w;
        }
        __syncthreads();
    }

    // stage transposed tile (n-major, b contiguous) then coalesced store
#pragma unroll
    for (int i = 0; i < 4; ++i)
#pragma unroll
        for (int j = 0; j < 4; ++j)
            Cs[tx * 4 + j][ty * 4 + i] = acc[i][j] + bp[n0 + tx * 4 + j];
    __syncthreads();

    const int crow = tid >> 4;   // 0..15
    const int cq   = tid & 15;   // 0..15
#pragma unroll
    for (int r = 0; r < 4; ++r) {
        int row = crow + r * 16;
        float4 v = *(float4*)&Cs[row][cq * 4];
        *(float4*)&g_Z[dir][t][n0 + row][cq * 4] = v;
    }
}

// ---------------- recurrence: persistent, software grid barrier per step ----------------
__device__ __forceinline__ float sigm(float v) { return 1.f / (1.f + __expf(-v)); }

#define REC_SMEM ((Hh * Bsz + 32 * Hh) * 4)   // 131072 + 65536 = 196608 bytes

__global__ void __launch_bounds__(512, 1)
rnn_kernel(float* __restrict__ out)
{
    extern __shared__ float sm[];
    float* hs = sm;                 // [Hh][Bsz]  h_prev staged, k-major
    float* Ws = sm + Hh * Bsz;      // [32][Hh]   4 gates x 8 n rows of Wt

    const int dir    = blockIdx.x >> 6;     // 0: fw, 1: bw   (128 blocks)
    const int blk    = blockIdx.x & 63;
    const int n_base = blk * 8;
    const int tid  = threadIdx.x;
    const int warp = tid >> 5, lane = tid & 31;
    const int n_idx = warp >> 1;                  // 0..7
    const int b     = ((warp & 1) << 5) + lane;   // 0..63
    const int n     = n_base + n_idx;

    // cache this block's 32 W rows (4 gates x 8 n) in smem, once
    for (int i = tid; i < 32 * Hh; i += 512) {
        int r = i >> 9;           // 0..31
        int k = i & 511;
        int gate = r >> 3, ni = r & 7;
        Ws[i] = g_Wt[dir][gate * Hh + n_base + ni][k];
    }
    const float* Wi = Ws + ((0 * 8 + n_idx) << 9);
    const float* Wj = Ws + ((1 * 8 + n_idx) << 9);
    const float* Wf = Ws + ((2 * 8 + n_idx) << 9);
    const float* Wo = Ws + ((3 * 8 + n_idx) << 9);
    const float* hsb = hs + b;

    float c = 0.f;
    __syncthreads();

    for (int t = 0; t < Tt; ++t) {
        // stage h_prev (bypass L1: written by other blocks within this launch)
        const float* hp = g_h[dir][t & 1];
        for (int i = (tid << 2); i < Hh * Bsz; i += (512 << 2)) {
            float4 v = __ldcg((const float4*)(hp + i));
            *(float4*)(hs + i) = v;
        }
        __syncthreads();

        const int tz = dir ? (Tt - 1 - t) : t;
        const float* z = &g_Z[dir][tz][0][0];
        float aI = z[(0 * Hh + n) * Bsz + b];
        float aJ = z[(1 * Hh + n) * Bsz + b];
        float aF = z[(2 * Hh + n) * Bsz + b];
        float aO = z[(3 * Hh + n) * Bsz + b];

#pragma unroll 2
        for (int k = 0; k < Hh; k += 4) {
            float4 wi = *(const float4*)(Wi + k);
            float4 wj = *(const float4*)(Wj + k);
            float4 wf = *(const float4*)(Wf + k);
            float4 wo = *(const float4*)(Wo + k);
            float h0 = hsb[(k + 0) * Bsz];
            float h1 = hsb[(k + 1) * Bsz];
            float h2 = hsb[(k + 2) * Bsz];
            float h3 = hsb[(k + 3) * Bsz];
            aI += wi.x * h0; aJ += wj.x * h0; aF += wf.x * h0; aO += wo.x * h0;
            aI += wi.y * h1; aJ += wj.y * h1; aF += wf.y * h1; aO += wo.y * h1;
            aI += wi.z * h2; aJ += wj.z * h2; aF += wf.z * h2; aO += wo.z * h2;
            aI += wi.w * h3; aJ += wj.w * h3; aF += wf.w * h3; aO += wo.w * h3;
        }

        // TF BasicLSTMCell: i, j, f, o with forget_bias = 1
        c = sigm(aF + 1.f) * c + sigm(aI) * tanhf(aJ);
        float hv = sigm(aO) * tanhf(c);

        g_h[dir][(t + 1) & 1][n * Bsz + b] = hv;
        out[((size_t)b * Tt + tz) * (2 * Hh) + dir * Hh + n] = hv;

        // grid-wide barrier (all 128 blocks resident: 192KB smem -> 1 block/SM)
        __threadfence();
        __syncthreads();
        if (tid == 0) {
            atomicAdd(&g_bar[t], 1u);
            while (*((volatile unsigned int*)&g_bar[t]) < 128u) { }
        }
        __syncthreads();
    }
}

// ---------------- launch ----------------
extern "C" void kernel_launch(void* const* d_in, const int* in_sizes, int n_in,
                              void* d_out, int out_size)
{
    const float* x   = (const float*)d_in[0];
    const float* Wfw = (const float*)d_in[1];
    const float* bfw = (const float*)d_in[2];
    const float* Wbw = (const float*)d_in[3];
    const float* bbw = (const float*)d_in[4];
    float* out = (float*)d_out;

    cudaFuncSetAttribute(rnn_kernel, cudaFuncAttributeMaxDynamicSharedMemorySize, REC_SMEM);

    init_kernel<<<512, 256>>>(Wfw, Wbw);

    dim3 pg(G4 / 64, Tt, 2);
    proj_kernel<<<pg, 256>>>(x, Wfw, bfw, Wbw, bbw);

    rnn_kernel<<<128, 512, REC_SMEM>>>(out);
}

// round 3
// speedup vs baseline: 1.2793x; 1.2793x over previous
#include <cuda_runtime.h>
#include <cuda_bf16.h>
#include <math.h>
#include <stdint.h>

#define Bsz 64
#define Tt  512
#define Dd  512
#define Hh  512
#define G4  2048   // 4*H

// ---------------- static device scratch (allocation-free rule) ----------------
__device__ float          g_Z[2][Tt][G4][Bsz];      // gate preactivations [dir][t][g][b] (512 MB)
__device__ float          g_Wt[2][G4][Hh];          // recurrent weights transposed (rec kernel)
__device__ float          g_h[2][2][Hh * Bsz];      // h double buffer
__device__ unsigned int   g_bar[Tt];                // grid barrier counters
__device__ __align__(128) __nv_bfloat16 g_xh[Bsz][Tt][Dd];   // x hi bf16
__device__ __align__(128) __nv_bfloat16 g_xl[Bsz][Tt][Dd];   // x lo bf16
__device__ __align__(128) __nv_bfloat16 g_Wsp[2][2][G4][Dd]; // proj W transposed [dir][hi/lo][g][k]

// ---------------- PTX helpers (baseline PTX only: sm_80-era features) ----------------
__device__ __forceinline__ uint32_t smem_u32(const void* p) {
    uint32_t a;
    asm("{ .reg .u64 t; cvta.to.shared.u64 t, %1; cvt.u32.u64 %0, t; }" : "=r"(a) : "l"(p));
    return a;
}
__device__ __forceinline__ void cpa16(uint32_t dst, const void* src) {
    asm volatile("cp.async.cg.shared.global [%0], [%1], 16;" :: "r"(dst), "l"(src));
}
__device__ __forceinline__ void cpa_commit() { asm volatile("cp.async.commit_group;"); }
template<int N> __device__ __forceinline__ void cpa_wait() {
    asm volatile("cp.async.wait_group %0;" :: "n"(N));
}
#define SWZ128(o) ((o) ^ (((o) >> 3) & 0x70))

__device__ __forceinline__ void ldm_x4(uint32_t* r, uint32_t addr) {
    asm volatile("ldmatrix.sync.aligned.m8n8.x4.shared.b16 {%0,%1,%2,%3}, [%4];"
        : "=r"(r[0]), "=r"(r[1]), "=r"(r[2]), "=r"(r[3]) : "r"(addr));
}
__device__ __forceinline__ void mma_bf16(float* d, const uint32_t* a, const uint32_t* b) {
    asm volatile("mma.sync.aligned.m16n8k16.row.col.f32.bf16.bf16.f32 "
        "{%0,%1,%2,%3}, {%4,%5,%6,%7}, {%8,%9}, {%0,%1,%2,%3};"
        : "+f"(d[0]), "+f"(d[1]), "+f"(d[2]), "+f"(d[3])
        : "r"(a[0]), "r"(a[1]), "r"(a[2]), "r"(a[3]), "r"(b[0]), "r"(b[1]));
}

// ---------------- init: transpose + split weights, split x, zero h / barrier ----------------
__global__ void init_kernel(const float* __restrict__ x,
                            const float* __restrict__ Wfw, const float* __restrict__ Wbw)
{
    int idx = blockIdx.x * blockDim.x + threadIdx.x;
    int stride = gridDim.x * blockDim.x;

    const int NWT = 2 * G4 * Hh;
    float* wt = &g_Wt[0][0][0];
    for (int i = idx; i < NWT; i += stride) {
        int dir = i / (G4 * Hh);
        int rem = i - dir * (G4 * Hh);
        int g = rem / Hh;
        int k = rem - g * Hh;
        const float* W = dir ? Wbw : Wfw;
        wt[i] = W[(size_t)(Dd + k) * G4 + g];
    }
    const int NWP = 2 * G4 * Dd;
    for (int i = idx; i < NWP; i += stride) {
        int dir = i / (G4 * Dd);
        int rem = i - dir * (G4 * Dd);
        int g = rem / Dd;
        int k = rem - g * Dd;
        const float* W = dir ? Wbw : Wfw;
        float w = W[(size_t)k * G4 + g];
        __nv_bfloat16 hi = __float2bfloat16(w);
        __nv_bfloat16 lo = __float2bfloat16(w - __bfloat162float(hi));
        g_Wsp[dir][0][g][k] = hi;
        g_Wsp[dir][1][g][k] = lo;
    }
    const int NX = Bsz * Tt * Dd;
    __nv_bfloat16* xh = &g_xh[0][0][0];
    __nv_bfloat16* xl = &g_xl[0][0][0];
    for (int i = idx; i < NX; i += stride) {
        float v = x[i];
        __nv_bfloat16 hi = __float2bfloat16(v);
        __nv_bfloat16 lo = __float2bfloat16(v - __bfloat162float(hi));
        xh[i] = hi;
        xl[i] = lo;
    }
    float* hh = &g_h[0][0][0];
    for (int i = idx; i < 2 * 2 * Hh * Bsz; i += stride) hh[i] = 0.f;
    for (int i = idx; i < Tt; i += stride) g_bar[i] = 0u;
}

// ---------------- proj: mma.sync bf16 3-term split GEMM ----------------
// Block tile M=128 (64 b x 2 t), N=128 gates, K chunks of 64 (SW128 rows of 128B).
// smem stage: Ah | Al | Bh | Bl, 16KB each -> 64KB/stage, double buffered.
#define OFF_AH 0
#define OFF_AL 16384
#define OFF_BH 32768
#define OFF_BL 49152
#define STAGE_BYTES 65536
#define PROJ_SMEM (2 * STAGE_BYTES + 1024)

__global__ void __launch_bounds__(256)
proj2_kernel(const float* __restrict__ bb0, const float* __restrict__ bb1)
{
    extern __shared__ char dsm[];
    char* dsa = (char*)(((uintptr_t)dsm + 1023ull) & ~1023ull);
    const uint32_t base = smem_u32(dsa);

    const int dir = blockIdx.z;
    const int t0  = blockIdx.y * 2;
    const int g0  = blockIdx.x * 128;
    const int tid = threadIdx.x;
    const int warp = tid >> 5, lane = tid & 31;
    const int warp_m = warp & 3;         // 0..3 -> m0 = warp_m*32
    const int warp_n = warp >> 2;        // 0..1 -> n0 = warp_n*64
    const float* bias = dir ? bb1 : bb0;

    // ---- chunk loader: fill one 64KB stage with Ah/Al/Bh/Bl for k0..k0+63 ----
    auto load_chunk = [&](uint32_t sb, int k0) {
#pragma unroll
        for (int i = 0; i < 4; ++i) {
            int q = i * 256 + tid;                 // 0..1023
            int row = q >> 3, c16 = q & 7;         // row 0..127, 16B unit 0..7
            uint32_t dsw = SWZ128(row * 128 + c16 * 16);
            int b = row & 63, dt = row >> 6;
            cpa16(sb + OFF_AH + dsw, (const char*)&g_xh[b][t0 + dt][k0] + c16 * 16);
            cpa16(sb + OFF_AL + dsw, (const char*)&g_xl[b][t0 + dt][k0] + c16 * 16);
            cpa16(sb + OFF_BH + dsw, (const char*)&g_Wsp[dir][0][g0 + row][k0] + c16 * 16);
            cpa16(sb + OFF_BL + dsw, (const char*)&g_Wsp[dir][1][g0 + row][k0] + c16 * 16);
        }
        cpa_commit();
    };

    float acc[2][8][4];
#pragma unroll
    for (int mt = 0; mt < 2; ++mt)
#pragma unroll
        for (int nt = 0; nt < 8; ++nt)
#pragma unroll
            for (int j = 0; j < 4; ++j) acc[mt][nt][j] = 0.f;

    load_chunk(base, 0);

    for (int chunk = 0; chunk < 8; ++chunk) {
        uint32_t sb = base + (chunk & 1) * STAGE_BYTES;
        if (chunk + 1 < 8) {
            load_chunk(base + ((chunk + 1) & 1) * STAGE_BYTES, (chunk + 1) * 64);
            cpa_wait<1>();
        } else {
            cpa_wait<0>();
        }
        __syncthreads();

        // precomputed intra-tile address components
        const int a_row = warp_m * 32 + (lane & 15);
        const int a_kof = (lane >> 4) * 8;                       // +0 or +8 elems
        const int b_row = warp_n * 64 + (lane & 7) + ((lane >> 4) << 3); // n within tile group
        const int b_kof = ((lane >> 3) & 1) * 8;

#pragma unroll
        for (int kk = 0; kk < 4; ++kk) {
            const int k0 = kk * 16;
            uint32_t ah[2][4], al[2][4], bh[16], bl[16];
#pragma unroll
            for (int mt = 0; mt < 2; ++mt) {
                uint32_t off = SWZ128((a_row + mt * 16) * 128 + (k0 + a_kof) * 2);
                ldm_x4(ah[mt], sb + OFF_AH + off);
                ldm_x4(al[mt], sb + OFF_AL + off);
            }
#pragma unroll
            for (int nq = 0; nq < 4; ++nq) {                      // each covers 16 n
                uint32_t off = SWZ128((b_row + nq * 16) * 128 + (k0 + b_kof) * 2);
                ldm_x4(&bh[nq * 4], sb + OFF_BH + off);
                ldm_x4(&bl[nq * 4], sb + OFF_BL + off);
            }
#pragma unroll
            for (int mt = 0; mt < 2; ++mt)
#pragma unroll
                for (int nt = 0; nt < 8; ++nt) {
                    mma_bf16(acc[mt][nt], ah[mt], &bh[nt * 2]);   // xh * Wh
                    mma_bf16(acc[mt][nt], al[mt], &bh[nt * 2]);   // xl * Wh
                    mma_bf16(acc[mt][nt], ah[mt], &bl[nt * 2]);   // xh * Wl
                }
        }
        __syncthreads();
    }

    // ---- epilogue: stage C[n][m] in smem (pitch 132), coalesced store to g_Z ----
    float* Cs = (float*)dsa;   // 128*132*4 = 67.5KB, stages no longer needed
#pragma unroll
    for (int mt = 0; mt < 2; ++mt)
#pragma unroll
        for (int nt = 0; nt < 8; ++nt) {
            int m = warp_m * 32 + mt * 16 + (lane >> 2);
            int n = warp_n * 64 + nt * 8 + (lane & 3) * 2;
            Cs[n * 132 + m]           = acc[mt][nt][0];
            Cs[(n + 1) * 132 + m]     = acc[mt][nt][1];
            Cs[n * 132 + m + 8]       = acc[mt][nt][2];
            Cs[(n + 1) * 132 + m + 8] = acc[mt][nt][3];
        }
    __syncthreads();

#pragma unroll
    for (int i = 0; i < 16; ++i) {
        int u = i * 256 + tid;                 // 0..4095
        int n = u >> 5;
        int r = u & 31;
        int dt = r >> 4, f4 = r & 15;
        float4 v = *(float4*)(Cs + n * 132 + dt * 64 + f4 * 4);
        float bv = bias[g0 + n];
        v.x += bv; v.y += bv; v.z += bv; v.w += bv;
        *(float4*)&g_Z[dir][t0 + dt][g0 + n][f4 * 4] = v;
    }
}

// ---------------- recurrence: persistent, software grid barrier per step ----------------
__device__ __forceinline__ float sigm(float v) { return 1.f / (1.f + __expf(-v)); }

#define REC_SMEM ((Hh * Bsz + 32 * Hh) * 4)

__global__ void __launch_bounds__(512, 1)
rnn_kernel(float* __restrict__ out)
{
    extern __shared__ float sm[];
    float* hs = sm;
    float* Ws = sm + Hh * Bsz;

    const int dir    = blockIdx.x >> 6;
    const int blk    = blockIdx.x & 63;
    const int n_base = blk * 8;
    const int tid  = threadIdx.x;
    const int warp = tid >> 5, lane = tid & 31;
    const int n_idx = warp >> 1;
    const int b     = ((warp & 1) << 5) + lane;
    const int n     = n_base + n_idx;

    for (int i = tid; i < 32 * Hh; i += 512) {
        int r = i >> 9;
        int k = i & 511;
        int gate = r >> 3, ni = r & 7;
        Ws[i] = g_Wt[dir][gate * Hh + n_base + ni][k];
    }
    const float* Wi = Ws + ((0 * 8 + n_idx) << 9);
    const float* Wj = Ws + ((1 * 8 + n_idx) << 9);
    const float* Wf = Ws + ((2 * 8 + n_idx) << 9);
    const float* Wo = Ws + ((3 * 8 + n_idx) << 9);
    const float* hsb = hs + b;

    float c = 0.f;
    __syncthreads();

    for (int t = 0; t < Tt; ++t) {
        const float* hp = g_h[dir][t & 1];
        for (int i = (tid << 2); i < Hh * Bsz; i += (512 << 2)) {
            float4 v = __ldcg((const float4*)(hp + i));
            *(float4*)(hs + i) = v;
        }
        __syncthreads();

        const int tz = dir ? (Tt - 1 - t) : t;
        const float* z = &g_Z[dir][tz][0][0];
        float aI = z[(0 * Hh + n) * Bsz + b];
        float aJ = z[(1 * Hh + n) * Bsz + b];
        float aF = z[(2 * Hh + n) * Bsz + b];
        float aO = z[(3 * Hh + n) * Bsz + b];

#pragma unroll 2
        for (int k = 0; k < Hh; k += 4) {
            float4 wi = *(const float4*)(Wi + k);
            float4 wj = *(const float4*)(Wj + k);
            float4 wf = *(const float4*)(Wf + k);
            float4 wo = *(const float4*)(Wo + k);
            float h0 = hsb[(k + 0) * Bsz];
            float h1 = hsb[(k + 1) * Bsz];
            float h2 = hsb[(k + 2) * Bsz];
            float h3 = hsb[(k + 3) * Bsz];
            aI += wi.x * h0; aJ += wj.x * h0; aF += wf.x * h0; aO += wo.x * h0;
            aI += wi.y * h1; aJ += wj.y * h1; aF += wf.y * h1; aO += wo.y * h1;
            aI += wi.z * h2; aJ += wj.z * h2; aF += wf.z * h2; aO += wo.z * h2;
            aI += wi.w * h3; aJ += wj.w * h3; aF += wf.w * h3; aO += wo.w * h3;
        }

        c = sigm(aF + 1.f) * c + sigm(aI) * tanhf(aJ);
        float hv = sigm(aO) * tanhf(c);

        g_h[dir][(t + 1) & 1][n * Bsz + b] = hv;
        out[((size_t)b * Tt + tz) * (2 * Hh) + dir * Hh + n] = hv;

        __threadfence();
        __syncthreads();
        if (tid == 0) {
            atomicAdd(&g_bar[t], 1u);
            while (*((volatile unsigned int*)&g_bar[t]) < 128u) { }
        }
        __syncthreads();
    }
}

// ---------------- launch ----------------
extern "C" void kernel_launch(void* const* d_in, const int* in_sizes, int n_in,
                              void* d_out, int out_size)
{
    const float* x   = (const float*)d_in[0];
    const float* Wfw = (const float*)d_in[1];
    const float* bfw = (const float*)d_in[2];
    const float* Wbw = (const float*)d_in[3];
    const float* bbw = (const float*)d_in[4];
    float* out = (float*)d_out;

    cudaFuncSetAttribute(rnn_kernel, cudaFuncAttributeMaxDynamicSharedMemorySize, REC_SMEM);
    cudaFuncSetAttribute(proj2_kernel, cudaFuncAttributeMaxDynamicSharedMemorySize, PROJ_SMEM);

    init_kernel<<<2048, 256>>>(x, Wfw, Wbw);

    dim3 pg(G4 / 128, Tt / 2, 2);
    proj2_kernel<<<pg, 256, PROJ_SMEM>>>(bfw, bbw);

    rnn_kernel<<<128, 512, REC_SMEM>>>(out);
}

// round 6
// speedup vs baseline: 2.8207x; 2.2049x over previous
#include <cuda_runtime.h>
#include <cuda_bf16.h>
#include <math.h>
#include <stdint.h>

#define Bsz 64
#define Tt  512
#define Dd  512
#define Hh  512
#define G4  2048   // 4*H

// ---------------- static device scratch (allocation-free rule) ----------------
__device__ float          g_Z[2][Tt][G4][Bsz];      // gate preactivations [dir][t][g][b] (512 MB)
__device__ unsigned int   g_bar[Tt];                // grid barrier counters
__device__ __align__(128) __nv_bfloat16 g_xh[Bsz][Tt][Dd];   // x hi bf16
__device__ __align__(128) __nv_bfloat16 g_xl[Bsz][Tt][Dd];   // x lo bf16
__device__ __align__(128) __nv_bfloat16 g_Wsp[2][2][G4][Dd]; // proj W transposed [dir][hi/lo][g][k]
__device__ __align__(128) __nv_bfloat16 g_Wr[2][64][2][32][512]; // rec W [dir][nb][hi/lo][col][k]
__device__ __align__(128) __nv_bfloat16 g_hh[2][Bsz][Hh];    // h hi bf16
__device__ __align__(128) __nv_bfloat16 g_hl[2][Bsz][Hh];    // h lo bf16

// ---------------- PTX helpers (baseline PTX only) ----------------
__device__ __forceinline__ uint32_t smem_u32(const void* p) {
    uint32_t a;
    asm("{ .reg .u64 t; cvta.to.shared.u64 t, %1; cvt.u32.u64 %0, t; }" : "=r"(a) : "l"(p));
    return a;
}
__device__ __forceinline__ void cpa16(uint32_t dst, const void* src) {
    asm volatile("cp.async.cg.shared.global [%0], [%1], 16;" :: "r"(dst), "l"(src));
}
__device__ __forceinline__ void cpa_commit() { asm volatile("cp.async.commit_group;"); }
template<int N> __device__ __forceinline__ void cpa_wait() {
    asm volatile("cp.async.wait_group %0;" :: "n"(N));
}
#define SWZ128(o) ((o) ^ (((o) >> 3) & 0x70))

__device__ __forceinline__ void ldm_x4(uint32_t* r, uint32_t addr) {
    asm volatile("ldmatrix.sync.aligned.m8n8.x4.shared.b16 {%0,%1,%2,%3}, [%4];"
        : "=r"(r[0]), "=r"(r[1]), "=r"(r[2]), "=r"(r[3]) : "r"(addr));
}
__device__ __forceinline__ void mma_bf16(float* d, const uint32_t* a, const uint32_t* b) {
    asm volatile("mma.sync.aligned.m16n8k16.row.col.f32.bf16.bf16.f32 "
        "{%0,%1,%2,%3}, {%4,%5,%6,%7}, {%8,%9}, {%0,%1,%2,%3};"
        : "+f"(d[0]), "+f"(d[1]), "+f"(d[2]), "+f"(d[3])
        : "r"(a[0]), "r"(a[1]), "r"(a[2]), "r"(a[3]), "r"(b[0]), "r"(b[1]));
}

// ---------------- init ----------------
__global__ void init_kernel(const float* __restrict__ x,
                            const float* __restrict__ Wfw, const float* __restrict__ Wbw)
{
    int idx = blockIdx.x * blockDim.x + threadIdx.x;
    int stride = gridDim.x * blockDim.x;

    // proj weight transpose + bf16 hi/lo split
    const int NWP = 2 * G4 * Dd;
    for (int i = idx; i < NWP; i += stride) {
        int dir = i / (G4 * Dd);
        int rem = i - dir * (G4 * Dd);
        int g = rem / Dd;
        int k = rem - g * Dd;
        const float* W = dir ? Wbw : Wfw;
        float w = W[(size_t)k * G4 + g];
        __nv_bfloat16 hi = __float2bfloat16(w);
        __nv_bfloat16 lo = __float2bfloat16(w - __bfloat162float(hi));
        g_Wsp[dir][0][g][k] = hi;
        g_Wsp[dir][1][g][k] = lo;
    }
    // recurrent weights: [dir][nb][s][col][k], col = gate*8 + ni
    const int NWR = 2 * 64 * 2 * 32 * 512;
    __nv_bfloat16* wr = &g_Wr[0][0][0][0][0];
    for (int i = idx; i < NWR; i += stride) {
        int k   = i & 511;
        int col = (i >> 9) & 31;
        int s   = (i >> 14) & 1;
        int nb  = (i >> 15) & 63;
        int dir = i >> 21;
        int gate = col >> 3, ni = col & 7;
        const float* W = dir ? Wbw : Wfw;
        float w = W[(size_t)(Dd + k) * G4 + gate * 512 + nb * 8 + ni];
        __nv_bfloat16 hi = __float2bfloat16(w);
        wr[i] = s ? __float2bfloat16(w - __bfloat162float(hi)) : hi;
    }
    // x hi/lo split
    const int NX = Bsz * Tt * Dd;
    __nv_bfloat16* xh = &g_xh[0][0][0];
    __nv_bfloat16* xl = &g_xl[0][0][0];
    for (int i = idx; i < NX; i += stride) {
        float v = x[i];
        __nv_bfloat16 hi = __float2bfloat16(v);
        __nv_bfloat16 lo = __float2bfloat16(v - __bfloat162float(hi));
        xh[i] = hi;
        xl[i] = lo;
    }
    // zero h, barriers
    __nv_bfloat16 z16 = __float2bfloat16(0.f);
    __nv_bfloat16* hh = &g_hh[0][0][0];
    __nv_bfloat16* hl = &g_hl[0][0][0];
    for (int i = idx; i < 2 * Bsz * Hh; i += stride) { hh[i] = z16; hl[i] = z16; }
    for (int i = idx; i < Tt; i += stride) g_bar[i] = 0u;
}

// ---------------- proj: mma.sync bf16 3-term split GEMM (unchanged from R3) ----------------
#define OFF_AH 0
#define OFF_AL 16384
#define OFF_BH 32768
#define OFF_BL 49152
#define STAGE_BYTES 65536
#define PROJ_SMEM (2 * STAGE_BYTES + 1024)

__global__ void __launch_bounds__(256)
proj2_kernel(const float* __restrict__ bb0, const float* __restrict__ bb1)
{
    extern __shared__ char dsm[];
    char* dsa = (char*)(((uintptr_t)dsm + 1023ull) & ~1023ull);
    const uint32_t base = smem_u32(dsa);

    const int dir = blockIdx.z;
    const int t0  = blockIdx.y * 2;
    const int g0  = blockIdx.x * 128;
    const int tid = threadIdx.x;
    const int warp = tid >> 5, lane = tid & 31;
    const int warp_m = warp & 3;
    const int warp_n = warp >> 2;
    const float* bias = dir ? bb1 : bb0;

    auto load_chunk = [&](uint32_t sb, int k0) {
#pragma unroll
        for (int i = 0; i < 4; ++i) {
            int q = i * 256 + tid;
            int row = q >> 3, c16 = q & 7;
            uint32_t dsw = SWZ128(row * 128 + c16 * 16);
            int b = row & 63, dt = row >> 6;
            cpa16(sb + OFF_AH + dsw, (const char*)&g_xh[b][t0 + dt][k0] + c16 * 16);
            cpa16(sb + OFF_AL + dsw, (const char*)&g_xl[b][t0 + dt][k0] + c16 * 16);
            cpa16(sb + OFF_BH + dsw, (const char*)&g_Wsp[dir][0][g0 + row][k0] + c16 * 16);
            cpa16(sb + OFF_BL + dsw, (const char*)&g_Wsp[dir][1][g0 + row][k0] + c16 * 16);
        }
        cpa_commit();
    };

    float acc[2][8][4];
#pragma unroll
    for (int mt = 0; mt < 2; ++mt)
#pragma unroll
        for (int nt = 0; nt < 8; ++nt)
#pragma unroll
            for (int j = 0; j < 4; ++j) acc[mt][nt][j] = 0.f;

    load_chunk(base, 0);

    for (int chunk = 0; chunk < 8; ++chunk) {
        uint32_t sb = base + (chunk & 1) * STAGE_BYTES;
        if (chunk + 1 < 8) {
            load_chunk(base + ((chunk + 1) & 1) * STAGE_BYTES, (chunk + 1) * 64);
            cpa_wait<1>();
        } else {
            cpa_wait<0>();
        }
        __syncthreads();

        const int a_row = warp_m * 32 + (lane & 15);
        const int a_kof = (lane >> 4) * 8;
        const int b_row = warp_n * 64 + (lane & 7) + ((lane >> 4) << 3);
        const int b_kof = ((lane >> 3) & 1) * 8;

#pragma unroll
        for (int kk = 0; kk < 4; ++kk) {
            const int k0 = kk * 16;
            uint32_t ah[2][4], al[2][4], bh[16], bl[16];
#pragma unroll
            for (int mt = 0; mt < 2; ++mt) {
                uint32_t off = SWZ128((a_row + mt * 16) * 128 + (k0 + a_kof) * 2);
                ldm_x4(ah[mt], sb + OFF_AH + off);
                ldm_x4(al[mt], sb + OFF_AL + off);
            }
#pragma unroll
            for (int nq = 0; nq < 4; ++nq) {
                uint32_t off = SWZ128((b_row + nq * 16) * 128 + (k0 + b_kof) * 2);
                ldm_x4(&bh[nq * 4], sb + OFF_BH + off);
                ldm_x4(&bl[nq * 4], sb + OFF_BL + off);
            }
#pragma unroll
            for (int mt = 0; mt < 2; ++mt)
#pragma unroll
                for (int nt = 0; nt < 8; ++nt) {
                    mma_bf16(acc[mt][nt], ah[mt], &bh[nt * 2]);
                    mma_bf16(acc[mt][nt], al[mt], &bh[nt * 2]);
                    mma_bf16(acc[mt][nt], ah[mt], &bl[nt * 2]);
                }
        }
        __syncthreads();
    }

    float* Cs = (float*)dsa;
#pragma unroll
    for (int mt = 0; mt < 2; ++mt)
#pragma unroll
        for (int nt = 0; nt < 8; ++nt) {
            int m = warp_m * 32 + mt * 16 + (lane >> 2);
            int n = warp_n * 64 + nt * 8 + (lane & 3) * 2;
            Cs[n * 132 + m]           = acc[mt][nt][0];
            Cs[(n + 1) * 132 + m]     = acc[mt][nt][1];
            Cs[n * 132 + m + 8]       = acc[mt][nt][2];
            Cs[(n + 1) * 132 + m + 8] = acc[mt][nt][3];
        }
    __syncthreads();

#pragma unroll
    for (int i = 0; i < 16; ++i) {
        int u = i * 256 + tid;
        int n = u >> 5;
        int r = u & 31;
        int dt = r >> 4, f4 = r & 15;
        float4 v = *(float4*)(Cs + n * 132 + dt * 64 + f4 * 4);
        float bv = bias[g0 + n];
        v.x += bv; v.y += bv; v.z += bv; v.w += bv;
        *(float4*)&g_Z[dir][t0 + dt][g0 + n][f4 * 4] = v;
    }
}

// ---------------- recurrence: persistent HMMA, grid barrier per step ----------------
__device__ __forceinline__ float sigm(float v) { return 1.f / (1.f + __expf(-v)); }

#define RA_HI 0
#define RA_LO 65536
#define RB_HI 131072
#define RB_LO 163840
#define RZS   196608
#define REC_SMEM (RZS + 8192)   // 204800 bytes

__global__ void __launch_bounds__(256, 1)
rnn_kernel(float* __restrict__ out)
{
    extern __shared__ char dsm[];
    const uint32_t base = smem_u32(dsm);
    float* Zs = (float*)(dsm + RZS);     // [32 cols][64 b]

    const int dir    = blockIdx.x >> 6;
    const int nb     = blockIdx.x & 63;
    const int n_base = nb * 8;
    const int tid  = threadIdx.x;
    const int warp = tid >> 5, lane = tid & 31;

    // ---- load recurrent weights once: 32 cols x 512 k, hi+lo, swizzled 64-k chunks ----
    for (int u = tid; u < 4096; u += 256) {
        int c16   = u & 7;
        int col   = (u >> 3) & 31;
        int chunk = (u >> 8) & 7;
        int s     = u >> 11;
        uint32_t dst = base + (s ? RB_LO : RB_HI) + chunk * 4096 + SWZ128(col * 128 + c16 * 16);
        cpa16(dst, &g_Wr[dir][nb][s][col][chunk * 64 + c16 * 8]);
    }
    cpa_commit();
    cpa_wait<0>();
    __syncthreads();

    const int bq = lane >> 2;          // 0..7
    const int n2 = (lane & 3) * 2;     // 0,2,4,6
    const int a_row = warp * 16 + (lane & 15);
    const int a_k8  = (lane >> 4) * 8;
    const int b_row = (lane & 7) + ((lane >> 4) << 3);
    const int b_k8  = ((lane >> 3) & 1) * 8;

    float cell[4] = {0.f, 0.f, 0.f, 0.f};

    for (int t = 0; t < Tt; ++t) {
        const int tz = dir ? (Tt - 1 - t) : t;

        // ---- stage A = h_t (bf16 hi/lo) into swizzled smem ----
        for (int u = tid; u < 8192; u += 256) {
            int c16   = u & 7;
            int row   = (u >> 3) & 63;
            int chunk = (u >> 9) & 7;
            int s     = u >> 12;
            uint32_t dst = base + (s ? RA_LO : RA_HI) + chunk * 8192 + SWZ128(row * 128 + c16 * 16);
            const __nv_bfloat16* src = s ? &g_hl[dir][row][chunk * 64 + c16 * 8]
                                         : &g_hh[dir][row][chunk * 64 + c16 * 8];
            cpa16(dst, src);
        }
        cpa_commit();

        // ---- warps 4-7: stage Z preactivations (32 cols x 64 b) ----
        if (warp >= 4) {
            int q = tid - 128;
#pragma unroll
            for (int i = 0; i < 4; ++i) {
                int u = i * 128 + q;
                int col = u >> 4;
                int f4  = u & 15;
                int gate = col >> 3, ni = col & 7;
                float4 v = *(const float4*)&g_Z[dir][tz][gate * 512 + n_base + ni][f4 * 4];
                *(float4*)&Zs[col * 64 + f4 * 4] = v;
            }
        }
        cpa_wait<0>();
        __syncthreads();

        if (warp < 4) {
            float acc[4][4];
#pragma unroll
            for (int g = 0; g < 4; ++g) {
                acc[g][0] = Zs[(g * 8 + n2    ) * 64 + warp * 16 + bq    ];
                acc[g][1] = Zs[(g * 8 + n2 + 1) * 64 + warp * 16 + bq    ];
                acc[g][2] = Zs[(g * 8 + n2    ) * 64 + warp * 16 + bq + 8];
                acc[g][3] = Zs[(g * 8 + n2 + 1) * 64 + warp * 16 + bq + 8];
            }

#pragma unroll 4
            for (int kt = 0; kt < 32; ++kt) {
                int chunk = kt >> 2;
                int kel   = (kt & 3) * 16;
                uint32_t ah[4], al[4], bh[8], bl[8];
                uint32_t aoff  = SWZ128(a_row * 128 + (kel + a_k8) * 2);
                ldm_x4(ah, base + RA_HI + chunk * 8192 + aoff);
                ldm_x4(al, base + RA_LO + chunk * 8192 + aoff);
                uint32_t boff0 = SWZ128(b_row * 128 + (kel + b_k8) * 2);
                uint32_t boff1 = SWZ128((b_row + 16) * 128 + (kel + b_k8) * 2);
                ldm_x4(&bh[0], base + RB_HI + chunk * 4096 + boff0);
                ldm_x4(&bh[4], base + RB_HI + chunk * 4096 + boff1);
                ldm_x4(&bl[0], base + RB_LO + chunk * 4096 + boff0);
                ldm_x4(&bl[4], base + RB_LO + chunk * 4096 + boff1);
#pragma unroll
                for (int g = 0; g < 4; ++g) {
                    mma_bf16(acc[g], ah, &bh[g * 2]);
                    mma_bf16(acc[g], al, &bh[g * 2]);
                    mma_bf16(acc[g], ah, &bl[g * 2]);
                }
            }

            // ---- pointwise cell update (i,j,f,o = acc[0..3], forget_bias=1) ----
#pragma unroll
            for (int c = 0; c < 4; ++c) {
                float iv = sigm(acc[0][c]);
                float jv = tanhf(acc[1][c]);
                float fv = sigm(acc[2][c] + 1.f);
                float ov = sigm(acc[3][c]);
                cell[c] = fv * cell[c] + iv * jv;
                float hv = ov * tanhf(cell[c]);
                int b = warp * 16 + bq + ((c >> 1) << 3);
                int n = n_base + n2 + (c & 1);
                __nv_bfloat16 hi = __float2bfloat16(hv);
                __nv_bfloat16 lo = __float2bfloat16(hv - __bfloat162float(hi));
                g_hh[dir][b][n] = hi;
                g_hl[dir][b][n] = lo;
                out[((size_t)b * Tt + tz) * (2 * Hh) + dir * Hh + n] = hv;
            }
        }

        // ---- grid barrier ----
        __threadfence();
        __syncthreads();
        if (tid == 0) {
            atomicAdd(&g_bar[t], 1u);
            while (*((volatile unsigned int*)&g_bar[t]) < 128u) { }
        }
        __syncthreads();
    }
}

// ---------------- launch ----------------
extern "C" void kernel_launch(void* const* d_in, const int* in_sizes, int n_in,
                              void* d_out, int out_size)
{
    const float* x   = (const float*)d_in[0];
    const float* Wfw = (const float*)d_in[1];
    const float* bfw = (const float*)d_in[2];
    const float* Wbw = (const float*)d_in[3];
    const float* bbw = (const float*)d_in[4];
    float* out = (float*)d_out;

    cudaFuncSetAttribute(rnn_kernel, cudaFuncAttributeMaxDynamicSharedMemorySize, REC_SMEM);
    cudaFuncSetAttribute(proj2_kernel, cudaFuncAttributeMaxDynamicSharedMemorySize, PROJ_SMEM);

    init_kernel<<<2048, 256>>>(x, Wfw, Wbw);

    dim3 pg(G4 / 128, Tt / 2, 2);
    proj2_kernel<<<pg, 256, PROJ_SMEM>>>(bfw, bbw);

    rnn_kernel<<<128, 256, REC_SMEM>>>(out);
}

// round 8
// speedup vs baseline: 2.9034x; 1.0293x over previous
#include <cuda_runtime.h>
#include <cuda_bf16.h>
#include <math.h>
#include <stdint.h>

#define Bsz 64
#define Tt  512
#define Dd  512
#define Hh  512
#define G4  2048   // 4*H

// ---------------- static device scratch (allocation-free rule) ----------------
__device__ float          g_Z[2][Tt][G4][Bsz];      // gate preactivations [dir][t][g][b] (512 MB)
__device__ unsigned int   g_bar[Tt];                // grid barrier counters
__device__ __align__(128) __nv_bfloat16 g_xh[Bsz][Tt][Dd];   // x hi bf16
__device__ __align__(128) __nv_bfloat16 g_xl[Bsz][Tt][Dd];   // x lo bf16
__device__ __align__(128) __nv_bfloat16 g_Wsp[2][2][G4][Dd]; // proj W transposed [dir][hi/lo][g][k]
__device__ __align__(128) __nv_bfloat16 g_Wr[2][64][2][32][512]; // rec W [dir][nb][hi/lo][col][k]
__device__ __align__(128) __nv_bfloat16 g_hh[2][Bsz][Hh];    // h hi bf16
__device__ __align__(128) __nv_bfloat16 g_hl[2][Bsz][Hh];    // h lo bf16

// ---------------- PTX helpers (baseline PTX only) ----------------
__device__ __forceinline__ uint32_t smem_u32(const void* p) {
    uint32_t a;
    asm("{ .reg .u64 t; cvta.to.shared.u64 t, %1; cvt.u32.u64 %0, t; }" : "=r"(a) : "l"(p));
    return a;
}
__device__ __forceinline__ void cpa16(uint32_t dst, const void* src) {
    asm volatile("cp.async.cg.shared.global [%0], [%1], 16;" :: "r"(dst), "l"(src));
}
__device__ __forceinline__ void cpa_commit() { asm volatile("cp.async.commit_group;"); }
template<int N> __device__ __forceinline__ void cpa_wait() {
    asm volatile("cp.async.wait_group %0;" :: "n"(N));
}
#define SWZ128(o) ((o) ^ (((o) >> 3) & 0x70))

__device__ __forceinline__ void ldm_x4(uint32_t* r, uint32_t addr) {
    asm volatile("ldmatrix.sync.aligned.m8n8.x4.shared.b16 {%0,%1,%2,%3}, [%4];"
        : "=r"(r[0]), "=r"(r[1]), "=r"(r[2]), "=r"(r[3]) : "r"(addr));
}
__device__ __forceinline__ void mma_bf16(float* d, const uint32_t* a, const uint32_t* b) {
    asm volatile("mma.sync.aligned.m16n8k16.row.col.f32.bf16.bf16.f32 "
        "{%0,%1,%2,%3}, {%4,%5,%6,%7}, {%8,%9}, {%0,%1,%2,%3};"
        : "+f"(d[0]), "+f"(d[1]), "+f"(d[2]), "+f"(d[3])
        : "r"(a[0]), "r"(a[1]), "r"(a[2]), "r"(a[3]), "r"(b[0]), "r"(b[1]));
}

// ---------------- init ----------------
__global__ void init_kernel(const float* __restrict__ x,
                            const float* __restrict__ Wfw, const float* __restrict__ Wbw)
{
    int idx = blockIdx.x * blockDim.x + threadIdx.x;
    int stride = gridDim.x * blockDim.x;

    const int NWP = 2 * G4 * Dd;
    for (int i = idx; i < NWP; i += stride) {
        int dir = i / (G4 * Dd);
        int rem = i - dir * (G4 * Dd);
        int g = rem / Dd;
        int k = rem - g * Dd;
        const float* W = dir ? Wbw : Wfw;
        float w = W[(size_t)k * G4 + g];
        __nv_bfloat16 hi = __float2bfloat16(w);
        __nv_bfloat16 lo = __float2bfloat16(w - __bfloat162float(hi));
        g_Wsp[dir][0][g][k] = hi;
        g_Wsp[dir][1][g][k] = lo;
    }
    const int NWR = 2 * 64 * 2 * 32 * 512;
    __nv_bfloat16* wr = &g_Wr[0][0][0][0][0];
    for (int i = idx; i < NWR; i += stride) {
        int k   = i & 511;
        int col = (i >> 9) & 31;
        int s   = (i >> 14) & 1;
        int nb  = (i >> 15) & 63;
        int dir = i >> 21;
        int gate = col >> 3, ni = col & 7;
        const float* W = dir ? Wbw : Wfw;
        float w = W[(size_t)(Dd + k) * G4 + gate * 512 + nb * 8 + ni];
        __nv_bfloat16 hi = __float2bfloat16(w);
        wr[i] = s ? __float2bfloat16(w - __bfloat162float(hi)) : hi;
    }
    const int NX = Bsz * Tt * Dd;
    __nv_bfloat16* xh = &g_xh[0][0][0];
    __nv_bfloat16* xl = &g_xl[0][0][0];
    for (int i = idx; i < NX; i += stride) {
        float v = x[i];
        __nv_bfloat16 hi = __float2bfloat16(v);
        __nv_bfloat16 lo = __float2bfloat16(v - __bfloat162float(hi));
        xh[i] = hi;
        xl[i] = lo;
    }
    __nv_bfloat16 z16 = __float2bfloat16(0.f);
    __nv_bfloat16* hh = &g_hh[0][0][0];
    __nv_bfloat16* hl = &g_hl[0][0][0];
    for (int i = idx; i < 2 * Bsz * Hh; i += stride) { hh[i] = z16; hl[i] = z16; }
    for (int i = idx; i < Tt; i += stride) g_bar[i] = 0u;
}

// ---------------- proj: mma.sync bf16 3-term split GEMM ----------------
// Block tile M=128 (64 b x 2 t), N=256 gates, 512 threads (16 warps, 4x4 warp grid).
// Stage: Ah 16K | Al 16K | Bh 32K | Bl 32K = 96KB, double-buffered = 192KB.
#define OFF_AH 0
#define OFF_AL 16384
#define OFF_BH 32768
#define OFF_BL 65536
#define STAGE_BYTES 98304
#define PROJ_SMEM (2 * STAGE_BYTES)

__global__ void __launch_bounds__(512)
proj2_kernel(const float* __restrict__ bb0, const float* __restrict__ bb1)
{
    extern __shared__ char dsm[];
    const uint32_t base = smem_u32(dsm);

    const int dir = blockIdx.z;
    const int t0  = blockIdx.y * 2;
    const int g0  = blockIdx.x * 256;
    const int tid = threadIdx.x;
    const int warp = tid >> 5, lane = tid & 31;
    const int warp_m = warp & 3;       // m0 = warp_m*32
    const int warp_n = warp >> 2;      // n0 = warp_n*64
    const float* bias = dir ? bb1 : bb0;

    // ---- chunk loader: A (128 rows x 64k, hi+lo) + B (256 rows x 64k, hi+lo) ----
    auto load_chunk = [&](uint32_t sb, int k0) {
#pragma unroll
        for (int i = 0; i < 4; ++i) {                 // A: 2048 16B-units
            int q = i * 512 + tid;
            int s = q >> 10, rem = q & 1023;
            int row = rem >> 3, c16 = rem & 7;
            uint32_t dsw = SWZ128(row * 128 + c16 * 16);
            int b = row & 63, dt = row >> 6;
            const __nv_bfloat16* src = s ? &g_xl[b][t0 + dt][k0 + c16 * 8]
                                         : &g_xh[b][t0 + dt][k0 + c16 * 8];
            cpa16(sb + (s ? OFF_AL : OFF_AH) + dsw, src);
        }
#pragma unroll
        for (int i = 0; i < 8; ++i) {                 // B: 4096 16B-units
            int q = i * 512 + tid;
            int s = q >> 11, rem = q & 2047;
            int row = rem >> 3, c16 = rem & 7;
            uint32_t dsw = SWZ128(row * 128 + c16 * 16);
            cpa16(sb + (s ? OFF_BL : OFF_BH) + dsw, &g_Wsp[dir][s][g0 + row][k0 + c16 * 8]);
        }
        cpa_commit();
    };

    float acc[2][8][4];
#pragma unroll
    for (int mt = 0; mt < 2; ++mt)
#pragma unroll
        for (int nt = 0; nt < 8; ++nt)
#pragma unroll
            for (int j = 0; j < 4; ++j) acc[mt][nt][j] = 0.f;

    load_chunk(base, 0);

    const int a_row = warp_m * 32 + (lane & 15);
    const int a_kof = (lane >> 4) * 8;
    const int b_row = warp_n * 64 + (lane & 7) + ((lane >> 4) << 3);
    const int b_kof = ((lane >> 3) & 1) * 8;

    for (int chunk = 0; chunk < 8; ++chunk) {
        uint32_t sb = base + (chunk & 1) * STAGE_BYTES;
        if (chunk + 1 < 8) {
            load_chunk(base + ((chunk + 1) & 1) * STAGE_BYTES, (chunk + 1) * 64);
            cpa_wait<1>();
        } else {
            cpa_wait<0>();
        }
        __syncthreads();

#pragma unroll
        for (int kk = 0; kk < 4; ++kk) {
            const int k0 = kk * 16;
            uint32_t ah[2][4], al[2][4], bh[16], bl[16];
#pragma unroll
            for (int mt = 0; mt < 2; ++mt) {
                uint32_t off = SWZ128((a_row + mt * 16) * 128 + (k0 + a_kof) * 2);
                ldm_x4(ah[mt], sb + OFF_AH + off);
                ldm_x4(al[mt], sb + OFF_AL + off);
            }
#pragma unroll
            for (int nq = 0; nq < 4; ++nq) {
                uint32_t off = SWZ128((b_row + nq * 16) * 128 + (k0 + b_kof) * 2);
                ldm_x4(&bh[nq * 4], sb + OFF_BH + off);
                ldm_x4(&bl[nq * 4], sb + OFF_BL + off);
            }
#pragma unroll
            for (int mt = 0; mt < 2; ++mt)
#pragma unroll
                for (int nt = 0; nt < 8; ++nt) {
                    mma_bf16(acc[mt][nt], ah[mt], &bh[nt * 2]);
                    mma_bf16(acc[mt][nt], al[mt], &bh[nt * 2]);
                    mma_bf16(acc[mt][nt], ah[mt], &bl[nt * 2]);
                }
        }
        __syncthreads();
    }

    // ---- epilogue: stage C[n][m] (pitch 132) then coalesced store to g_Z ----
    float* Cs = (float*)dsm;   // 256*132*4 = 135KB, stages no longer needed
#pragma unroll
    for (int mt = 0; mt < 2; ++mt)
#pragma unroll
        for (int nt = 0; nt < 8; ++nt) {
            int m = warp_m * 32 + mt * 16 + (lane >> 2);
            int n = warp_n * 64 + nt * 8 + (lane & 3) * 2;
            Cs[n * 132 + m]           = acc[mt][nt][0];
            Cs[(n + 1) * 132 + m]     = acc[mt][nt][1];
            Cs[n * 132 + m + 8]       = acc[mt][nt][2];
            Cs[(n + 1) * 132 + m + 8] = acc[mt][nt][3];
        }
    __syncthreads();

#pragma unroll
    for (int i = 0; i < 16; ++i) {
        int u = i * 512 + tid;                 // 0..8191 float4 units
        int n = u >> 5;
        int r = u & 31;
        int dt = r >> 4, f4 = r & 15;
        float4 v = *(float4*)(Cs + n * 132 + dt * 64 + f4 * 4);
        float bv = bias[g0 + n];
        v.x += bv; v.y += bv; v.z += bv; v.w += bv;
        *(float4*)&g_Z[dir][t0 + dt][g0 + n][f4 * 4] = v;
    }
}

// ---------------- recurrence: persistent HMMA, grid barrier per step (unchanged) ----------------
__device__ __forceinline__ float sigm(float v) { return 1.f / (1.f + __expf(-v)); }

#define RA_HI 0
#define RA_LO 65536
#define RB_HI 131072
#define RB_LO 163840
#define RZS   196608
#define REC_SMEM (RZS + 8192)   // 204800 bytes

__global__ void __launch_bounds__(256, 1)
rnn_kernel(float* __restrict__ out)
{
    extern __shared__ char dsm[];
    const uint32_t base = smem_u32(dsm);
    float* Zs = (float*)(dsm + RZS);

    const int dir    = blockIdx.x >> 6;
    const int nb     = blockIdx.x & 63;
    const int n_base = nb * 8;
    const int tid  = threadIdx.x;
    const int warp = tid >> 5, lane = tid & 31;

    for (int u = tid; u < 4096; u += 256) {
        int c16   = u & 7;
        int col   = (u >> 3) & 31;
        int chunk = (u >> 8) & 7;
        int s     = u >> 11;
        uint32_t dst = base + (s ? RB_LO : RB_HI) + chunk * 4096 + SWZ128(col * 128 + c16 * 16);
        cpa16(dst, &g_Wr[dir][nb][s][col][chunk * 64 + c16 * 8]);
    }
    cpa_commit();
    cpa_wait<0>();
    __syncthreads();

    const int bq = lane >> 2;
    const int n2 = (lane & 3) * 2;
    const int a_row = warp * 16 + (lane & 15);
    const int a_k8  = (lane >> 4) * 8;
    const int b_row = (lane & 7) + ((lane >> 4) << 3);
    const int b_k8  = ((lane >> 3) & 1) * 8;

    float cell[4] = {0.f, 0.f, 0.f, 0.f};

    for (int t = 0; t < Tt; ++t) {
        const int tz = dir ? (Tt - 1 - t) : t;

        for (int u = tid; u < 8192; u += 256) {
            int c16   = u & 7;
            int row   = (u >> 3) & 63;
            int chunk = (u >> 9) & 7;
            int s     = u >> 12;
            uint32_t dst = base + (s ? RA_LO : RA_HI) + chunk * 8192 + SWZ128(row * 128 + c16 * 16);
            const __nv_bfloat16* src = s ? &g_hl[dir][row][chunk * 64 + c16 * 8]
                                         : &g_hh[dir][row][chunk * 64 + c16 * 8];
            cpa16(dst, src);
        }
        cpa_commit();

        if (warp >= 4) {
            int q = tid - 128;
#pragma unroll
            for (int i = 0; i < 4; ++i) {
                int u = i * 128 + q;
                int col = u >> 4;
                int f4  = u & 15;
                int gate = col >> 3, ni = col & 7;
                float4 v = *(const float4*)&g_Z[dir][tz][gate * 512 + n_base + ni][f4 * 4];
                *(float4*)&Zs[col * 64 + f4 * 4] = v;
            }
        }
        cpa_wait<0>();
        __syncthreads();

        if (warp < 4) {
            float acc[4][4];
#pragma unroll
            for (int g = 0; g < 4; ++g) {
                acc[g][0] = Zs[(g * 8 + n2    ) * 64 + warp * 16 + bq    ];
                acc[g][1] = Zs[(g * 8 + n2 + 1) * 64 + warp * 16 + bq    ];
                acc[g][2] = Zs[(g * 8 + n2    ) * 64 + warp * 16 + bq + 8];
                acc[g][3] = Zs[(g * 8 + n2 + 1) * 64 + warp * 16 + bq + 8];
            }

#pragma unroll 4
            for (int kt = 0; kt < 32; ++kt) {
                int chunk = kt >> 2;
                int kel   = (kt & 3) * 16;
                uint32_t ah[4], al[4], bh[8], bl[8];
                uint32_t aoff  = SWZ128(a_row * 128 + (kel + a_k8) * 2);
                ldm_x4(ah, base + RA_HI + chunk * 8192 + aoff);
                ldm_x4(al, base + RA_LO + chunk * 8192 + aoff);
                uint32_t boff0 = SWZ128(b_row * 128 + (kel + b_k8) * 2);
                uint32_t boff1 = SWZ128((b_row + 16) * 128 + (kel + b_k8) * 2);
                ldm_x4(&bh[0], base + RB_HI + chunk * 4096 + boff0);
                ldm_x4(&bh[4], base + RB_HI + chunk * 4096 + boff1);
                ldm_x4(&bl[0], base + RB_LO + chunk * 4096 + boff0);
                ldm_x4(&bl[4], base + RB_LO + chunk * 4096 + boff1);
#pragma unroll
                for (int g = 0; g < 4; ++g) {
                    mma_bf16(acc[g], ah, &bh[g * 2]);
                    mma_bf16(acc[g], al, &bh[g * 2]);
                    mma_bf16(acc[g], ah, &bl[g * 2]);
                }
            }

#pragma unroll
            for (int c = 0; c < 4; ++c) {
                float iv = sigm(acc[0][c]);
                float jv = tanhf(acc[1][c]);
                float fv = sigm(acc[2][c] + 1.f);
                float ov = sigm(acc[3][c]);
                cell[c] = fv * cell[c] + iv * jv;
                float hv = ov * tanhf(cell[c]);
                int b = warp * 16 + bq + ((c >> 1) << 3);
                int n = n_base + n2 + (c & 1);
                __nv_bfloat16 hi = __float2bfloat16(hv);
                __nv_bfloat16 lo = __float2bfloat16(hv - __bfloat162float(hi));
                g_hh[dir][b][n] = hi;
                g_hl[dir][b][n] = lo;
                out[((size_t)b * Tt + tz) * (2 * Hh) + dir * Hh + n] = hv;
            }
        }

        __threadfence();
        __syncthreads();
        if (tid == 0) {
            atomicAdd(&g_bar[t], 1u);
            while (*((volatile unsigned int*)&g_bar[t]) < 128u) { }
        }
        __syncthreads();
    }
}

// ---------------- launch ----------------
extern "C" void kernel_launch(void* const* d_in, const int* in_sizes, int n_in,
                              void* d_out, int out_size)
{
    const float* x   = (const float*)d_in[0];
    const float* Wfw = (const float*)d_in[1];
    const float* bfw = (const float*)d_in[2];
    const float* Wbw = (const float*)d_in[3];
    const float* bbw = (const float*)d_in[4];
    float* out = (float*)d_out;

    cudaFuncSetAttribute(rnn_kernel, cudaFuncAttributeMaxDynamicSharedMemorySize, REC_SMEM);
    cudaFuncSetAttribute(proj2_kernel, cudaFuncAttributeMaxDynamicSharedMemorySize, PROJ_SMEM);

    init_kernel<<<2048, 256>>>(x, Wfw, Wbw);

    dim3 pg(G4 / 256, Tt / 2, 2);
    proj2_kernel<<<pg, 512, PROJ_SMEM>>>(bfw, bbw);

    rnn_kernel<<<128, 256, REC_SMEM>>>(out);
}

// round 9
// speedup vs baseline: 3.1763x; 1.0940x over previous
#include <cuda_runtime.h>
#include <cuda_bf16.h>
#include <math.h>
#include <stdint.h>

#define Bsz 64
#define Tt  512
#define Dd  512
#define Hh  512
#define G4  2048   // 4*H

// ---------------- static device scratch (allocation-free rule) ----------------
__device__ unsigned int   g_bar[Tt];                // grid barrier counters
__device__ __align__(128) __nv_bfloat16 g_xh[Bsz][Tt][Dd];   // x hi bf16
__device__ __align__(128) __nv_bfloat16 g_xl[Bsz][Tt][Dd];   // x lo bf16
__device__ __align__(128) __nv_bfloat16 g_Wr[2][64][2][32][512]; // rec W [dir][nb][hi/lo][col][k]
__device__ __align__(128) __nv_bfloat16 g_Wx[2][64][2][32][512]; // proj W, same layout, k over D
__device__ __align__(128) __nv_bfloat16 g_hh[2][Bsz][Hh];    // h hi bf16
__device__ __align__(128) __nv_bfloat16 g_hl[2][Bsz][Hh];    // h lo bf16

// ---------------- PTX helpers (baseline PTX only) ----------------
__device__ __forceinline__ uint32_t smem_u32(const void* p) {
    uint32_t a;
    asm("{ .reg .u64 t; cvta.to.shared.u64 t, %1; cvt.u32.u64 %0, t; }" : "=r"(a) : "l"(p));
    return a;
}
__device__ __forceinline__ void cpa16(uint32_t dst, const void* src) {
    asm volatile("cp.async.cg.shared.global [%0], [%1], 16;" :: "r"(dst), "l"(src));
}
__device__ __forceinline__ void cpa_commit() { asm volatile("cp.async.commit_group;"); }
template<int N> __device__ __forceinline__ void cpa_wait() {
    asm volatile("cp.async.wait_group %0;" :: "n"(N));
}
__device__ __forceinline__ void barg(int id) {
    asm volatile("bar.sync %0, %1;" :: "r"(id), "r"(128) : "memory");
}
#define SWZ128(o) ((o) ^ (((o) >> 3) & 0x70))

__device__ __forceinline__ void ldm_x4(uint32_t* r, uint32_t addr) {
    asm volatile("ldmatrix.sync.aligned.m8n8.x4.shared.b16 {%0,%1,%2,%3}, [%4];"
        : "=r"(r[0]), "=r"(r[1]), "=r"(r[2]), "=r"(r[3]) : "r"(addr));
}
__device__ __forceinline__ void mma_bf16(float* d, const uint32_t* a, const uint32_t* b) {
    asm volatile("mma.sync.aligned.m16n8k16.row.col.f32.bf16.bf16.f32 "
        "{%0,%1,%2,%3}, {%4,%5,%6,%7}, {%8,%9}, {%0,%1,%2,%3};"
        : "+f"(d[0]), "+f"(d[1]), "+f"(d[2]), "+f"(d[3])
        : "r"(a[0]), "r"(a[1]), "r"(a[2]), "r"(a[3]), "r"(b[0]), "r"(b[1]));
}

// ---------------- init ----------------
__global__ void init_kernel(const float* __restrict__ x,
                            const float* __restrict__ Wfw, const float* __restrict__ Wbw)
{
    int idx = blockIdx.x * blockDim.x + threadIdx.x;
    int stride = gridDim.x * blockDim.x;

    // rec + proj weights: [dir][nb][s][col][k], col = gate*8 + ni
    const int NW = 2 * 64 * 2 * 32 * 512;
    __nv_bfloat16* wr = &g_Wr[0][0][0][0][0];
    __nv_bfloat16* wx = &g_Wx[0][0][0][0][0];
    for (int i = idx; i < NW; i += stride) {
        int k   = i & 511;
        int col = (i >> 9) & 31;
        int s   = (i >> 14) & 1;
        int nb  = (i >> 15) & 63;
        int dir = i >> 21;
        int gate = col >> 3, ni = col & 7;
        const float* W = dir ? Wbw : Wfw;
        int gcol = gate * 512 + nb * 8 + ni;
        float wrv = W[(size_t)(Dd + k) * G4 + gcol];
        float wxv = W[(size_t)k * G4 + gcol];
        __nv_bfloat16 rh = __float2bfloat16(wrv);
        __nv_bfloat16 xh2 = __float2bfloat16(wxv);
        wr[i] = s ? __float2bfloat16(wrv - __bfloat162float(rh)) : rh;
        wx[i] = s ? __float2bfloat16(wxv - __bfloat162float(xh2)) : xh2;
    }
    const int NX = Bsz * Tt * Dd;
    __nv_bfloat16* xh = &g_xh[0][0][0];
    __nv_bfloat16* xl = &g_xl[0][0][0];
    for (int i = idx; i < NX; i += stride) {
        float v = x[i];
        __nv_bfloat16 hi = __float2bfloat16(v);
        __nv_bfloat16 lo = __float2bfloat16(v - __bfloat162float(hi));
        xh[i] = hi;
        xl[i] = lo;
    }
    __nv_bfloat16 z16 = __float2bfloat16(0.f);
    __nv_bfloat16* hh = &g_hh[0][0][0];
    __nv_bfloat16* hl = &g_hl[0][0][0];
    for (int i = idx; i < 2 * Bsz * Hh; i += stride) { hh[i] = z16; hl[i] = z16; }
    for (int i = idx; i < Tt; i += stride) g_bar[i] = 0u;
}

// ---------------- fused persistent kernel ----------------
// smem: [SB_REC 64K][SB_X 64K][SA_H 32K][SA_X 32K][SZX 16K] = 208KB, 1 CTA/SM.
// warps 0-3: h-GEMM step t (seeded from sZx parity t&1) + pointwise + h/out stores.
// warps 4-7: x-GEMM for step t+1 -> sZx parity (t+1)&1, bias folded in.
#define SB_REC 0
#define SB_X   65536
#define SA_H   131072
#define SA_X   163840
#define SZX    196608
#define FUSED_SMEM 212992

__device__ __forceinline__ float sigm(float v) { return 1.f / (1.f + __expf(-v)); }

__global__ void __launch_bounds__(256, 1)
rnn_fused(float* __restrict__ out, const float* __restrict__ bfw, const float* __restrict__ bbw)
{
    extern __shared__ char dsm[];
    const uint32_t base = smem_u32(dsm);
    float* sZx = (float*)(dsm + SZX);    // [parity][32 cols][64 b]

    const int dir    = blockIdx.x >> 6;
    const int nb     = blockIdx.x & 63;
    const int n_base = nb * 8;
    const int tid  = threadIdx.x;
    const int warp = tid >> 5, lane = tid & 31;
    const int wg   = warp & 3;           // warp index within its group
    const bool isH = warp < 4;
    const int qid  = isH ? tid : tid - 128;   // 0..127 within group

    // ---- load B weights (rec + x, hi/lo) once: 8192 16B units ----
    for (int u = tid; u < 8192; u += 256) {
        int which = u >> 12;             // 0 rec, 1 x
        int rem   = u & 4095;
        int s     = rem >> 11;
        int r2    = rem & 2047;
        int c16   = r2 & 7;
        int col   = (r2 >> 3) & 31;
        int chunk = r2 >> 8;
        const __nv_bfloat16* src = which ? &g_Wx[dir][nb][s][col][chunk * 64 + c16 * 8]
                                         : &g_Wr[dir][nb][s][col][chunk * 64 + c16 * 8];
        cpa16(base + which * 65536 + s * 32768 + chunk * 4096 + SWZ128(col * 128 + c16 * 16), src);
    }
    cpa_commit();
    cpa_wait<0>();
    __syncthreads();

    // fragment geometry (shared by both groups)
    const int bq = lane >> 2;
    const int n2 = (lane & 3) * 2;
    const int a_row = wg * 16 + (lane & 15);
    const int a_k8  = (lane >> 4) * 8;
    const int b_row = (lane & 7) + ((lane >> 4) << 3);
    const int b_k8  = ((lane >> 3) & 1) * 8;

    // bias registers for x-warps
    float breg[4][2];
    if (!isH) {
        const float* bb = dir ? bbw : bfw;
#pragma unroll
        for (int g = 0; g < 4; ++g) {
            breg[g][0] = bb[g * 512 + n_base + n2];
            breg[g][1] = bb[g * 512 + n_base + n2 + 1];
        }
    }

    // ---- staging helpers: one 16KB chunk (hi+lo) by 128 threads, 8 cpa16 each ----
    auto stage_h = [&](int c, int st) {
#pragma unroll
        for (int i = 0; i < 8; ++i) {
            int u = i * 128 + qid;
            int s = u >> 9, rem = u & 511;
            int row = rem >> 3, c16 = rem & 7;
            const __nv_bfloat16* src = s ? &g_hl[dir][row][c * 64 + c16 * 8]
                                         : &g_hh[dir][row][c * 64 + c16 * 8];
            cpa16(base + SA_H + st * 16384 + s * 8192 + SWZ128(row * 128 + c16 * 16), src);
        }
        cpa_commit();
    };
    auto stage_x = [&](int c, int st, int tzn) {
#pragma unroll
        for (int i = 0; i < 8; ++i) {
            int u = i * 128 + qid;
            int s = u >> 9, rem = u & 511;
            int row = rem >> 3, c16 = rem & 7;
            const __nv_bfloat16* src = s ? &g_xl[row][tzn][c * 64 + c16 * 8]
                                         : &g_xh[row][tzn][c * 64 + c16 * 8];
            cpa16(base + SA_X + st * 16384 + s * 8192 + SWZ128(row * 128 + c16 * 16), src);
        }
        cpa_commit();
    };

    auto compute_chunk = [&](float (*acc)[4], uint32_t aB, uint32_t bB, int c) {
#pragma unroll
        for (int kt = 0; kt < 4; ++kt) {
            const int kel = kt * 16;
            uint32_t ah[4], al[4], bh[8], bl[8];
            uint32_t aoff = SWZ128(a_row * 128 + (kel + a_k8) * 2);
            ldm_x4(ah, aB + aoff);
            ldm_x4(al, aB + 8192 + aoff);
            uint32_t boff0 = SWZ128(b_row * 128 + (kel + b_k8) * 2);
            uint32_t boff1 = SWZ128((b_row + 16) * 128 + (kel + b_k8) * 2);
            ldm_x4(&bh[0], bB + c * 4096 + boff0);
            ldm_x4(&bh[4], bB + c * 4096 + boff1);
            ldm_x4(&bl[0], bB + 32768 + c * 4096 + boff0);
            ldm_x4(&bl[4], bB + 32768 + c * 4096 + boff1);
#pragma unroll
            for (int g = 0; g < 4; ++g) {
                mma_bf16(acc[g], ah, &bh[g * 2]);
                mma_bf16(acc[g], al, &bh[g * 2]);
                mma_bf16(acc[g], ah, &bl[g * 2]);
            }
        }
    };

    // ---- x-GEMM pipeline (warps 4-7): preactivations for x[tzn] -> sZx[par] ----
    auto xgemm = [&](int tzn, int par) {
        float acc[4][4];
#pragma unroll
        for (int g = 0; g < 4; ++g) {
            acc[g][0] = breg[g][0]; acc[g][1] = breg[g][1];
            acc[g][2] = breg[g][0]; acc[g][3] = breg[g][1];
        }
        stage_x(0, 0, tzn);
        stage_x(1, 1, tzn);
        for (int c = 0; c < 8; ++c) {
            if (c < 7) cpa_wait<1>(); else cpa_wait<0>();
            barg(2);
            compute_chunk(acc, base + SA_X + (c & 1) * 16384, base + SB_X, c);
            if (c < 6) { barg(2); stage_x(c + 2, c & 1, tzn); }
        }
        float* zx = sZx + par * 2048;
#pragma unroll
        for (int g = 0; g < 4; ++g) {
            int col0 = (g * 8 + n2) * 64, col1 = (g * 8 + n2 + 1) * 64;
            int m = wg * 16 + bq;
            zx[col0 + m]     = acc[g][0];
            zx[col1 + m]     = acc[g][1];
            zx[col0 + m + 8] = acc[g][2];
            zx[col1 + m + 8] = acc[g][3];
        }
    };

    // ---- prologue: x preactivations for step 0 ----
    if (!isH) xgemm(dir ? (Tt - 1) : 0, 0);
    __syncthreads();

    float cell[4] = {0.f, 0.f, 0.f, 0.f};

    for (int t = 0; t < Tt; ++t) {
        const int tz = dir ? (Tt - 1 - t) : t;

        if (isH) {
            // h-GEMM for step t
            stage_h(0, 0);
            stage_h(1, 1);
            float acc[4][4];
            const float* zx = sZx + (t & 1) * 2048;
#pragma unroll
            for (int g = 0; g < 4; ++g) {
                int col0 = (g * 8 + n2) * 64, col1 = (g * 8 + n2 + 1) * 64;
                int m = wg * 16 + bq;
                acc[g][0] = zx[col0 + m];
                acc[g][1] = zx[col1 + m];
                acc[g][2] = zx[col0 + m + 8];
                acc[g][3] = zx[col1 + m + 8];
            }
            for (int c = 0; c < 8; ++c) {
                if (c < 7) cpa_wait<1>(); else cpa_wait<0>();
                barg(1);
                compute_chunk(acc, base + SA_H + (c & 1) * 16384, base + SB_REC, c);
                if (c < 6) { barg(1); stage_h(c + 2, c & 1); }
            }
            // pointwise (i,j,f,o, forget_bias=1)
#pragma unroll
            for (int c = 0; c < 4; ++c) {
                float iv = sigm(acc[0][c]);
                float jv = tanhf(acc[1][c]);
                float fv = sigm(acc[2][c] + 1.f);
                float ov = sigm(acc[3][c]);
                cell[c] = fv * cell[c] + iv * jv;
                float hv = ov * tanhf(cell[c]);
                int b = wg * 16 + bq + ((c >> 1) << 3);
                int n = n_base + n2 + (c & 1);
                __nv_bfloat16 hi = __float2bfloat16(hv);
                __nv_bfloat16 lo = __float2bfloat16(hv - __bfloat162float(hi));
                g_hh[dir][b][n] = hi;
                g_hl[dir][b][n] = lo;
                out[((size_t)b * Tt + tz) * (2 * Hh) + dir * Hh + n] = hv;
            }
        } else {
            // x-GEMM for step t+1
            if (t + 1 < Tt) {
                int tzn = dir ? (Tt - 2 - t) : (t + 1);
                xgemm(tzn, (t + 1) & 1);
            }
        }

        // ---- grid barrier ----
        __threadfence();
        __syncthreads();
        if (tid == 0) {
            atomicAdd(&g_bar[t], 1u);
            while (*((volatile unsigned int*)&g_bar[t]) < 128u) { }
        }
        __syncthreads();
    }
}

// ---------------- launch ----------------
extern "C" void kernel_launch(void* const* d_in, const int* in_sizes, int n_in,
                              void* d_out, int out_size)
{
    const float* x   = (const float*)d_in[0];
    const float* Wfw = (const float*)d_in[1];
    const float* bfw = (const float*)d_in[2];
    const float* Wbw = (const float*)d_in[3];
    const float* bbw = (const float*)d_in[4];
    float* out = (float*)d_out;

    cudaFuncSetAttribute(rnn_fused, cudaFuncAttributeMaxDynamicSharedMemorySize, FUSED_SMEM);

    init_kernel<<<2048, 256>>>(x, Wfw, Wbw);
    rnn_fused<<<128, 256, FUSED_SMEM>>>(out, bfw, bbw);
}